// round 15
// baseline (speedup 1.0000x reference)
#include <cuda_runtime.h>
#include <cuda/atomic>
#include <cstdint>

#define TSTEPS 300
#define HIDN   512
#define EMBD   300
#define G4     2048      // 4*HIDN
#define NCTA   32
#define TPB    512
#define SPIN_GUARD (1 << 16)

typedef unsigned long long u64;

// ---------------- scratch (static __device__, no allocs) ----------------
__device__ __align__(16) float g_pre[TSTEPS * G4]; // input-side gates (+biases)
__device__ __align__(16) u64   g_hw[2][HIDN];      // tagged hidden words: (tag<<32)|bits
                                                   // tag s = "h after s steps"

using dev_atomic_u64 = cuda::atomic_ref<u64, cuda::thread_scope_device>;

__device__ __forceinline__ u64 pack_h(float v, unsigned tag) {
    return ((u64)tag << 32) | (u64)__float_as_uint(v);
}

__device__ __forceinline__ float sigm(float x) { return 1.f / (1.f + __expf(-x)); }
__device__ __forceinline__ float tanh_f(float x) {
    // overflow-safe: tanh(x) = sign(x) * (1 - 2/(exp(2|x|)+1))
    float e = __expf(2.f * fabsf(x));
    float r = 1.f - 2.f / (e + 1.f);
    return copysignf(r, x);
}

// ================= Phase 1: pre[t][row] = W_ih @ emb[x[t]] + b_ih + b_hh ==========
// grid (128, 19), block 256.  Block covers 16 rows x 16 timesteps; K=300 loop.
__global__ void pre_kernel(const int* __restrict__ x,
                           const float* __restrict__ emb,
                           const float* __restrict__ W_ih,
                           const float* __restrict__ b_ih,
                           const float* __restrict__ b_hh,
                           const float* __restrict__ h0)
{
    __shared__ float E[16][301];   // stride 301 -> conflict-free column reads
    const int tB = blockIdx.y * 16;
    const int rB = blockIdx.x * 16;

    for (int idx = threadIdx.x; idx < 16 * EMBD; idx += 256) {
        int tt = idx / EMBD, k = idx % EMBD;
        int t = tB + tt;
        E[tt][k] = (t < TSTEPS) ? emb[(size_t)x[t] * EMBD + k] : 0.f;
    }
    __syncthreads();

    const int t_local = threadIdx.x & 15;
    const int r_local = threadIdx.x >> 4;
    const int r = rB + r_local;
    const int t = tB + t_local;

    const float* wr = W_ih + (size_t)r * EMBD;
    float a0 = 0.f, a1 = 0.f, a2 = 0.f, a3 = 0.f;
    #pragma unroll 4
    for (int k = 0; k < EMBD; k += 4) {
        a0 = fmaf(wr[k + 0], E[t_local][k + 0], a0);
        a1 = fmaf(wr[k + 1], E[t_local][k + 1], a1);
        a2 = fmaf(wr[k + 2], E[t_local][k + 2], a2);
        a3 = fmaf(wr[k + 3], E[t_local][k + 3], a3);
    }
    if (t < TSTEPS)
        g_pre[(size_t)t * G4 + r] = (a0 + a1) + (a2 + a3) + b_ih[r] + b_hh[r];

    // block (0,0): seed h words with tag 0 and poison the other buffer's tags
    // (kills any cross-replay tag collision)
    if (blockIdx.x == 0 && blockIdx.y == 0) {
        for (int i = threadIdx.x; i < HIDN; i += 256) {
            dev_atomic_u64 a0ref(g_hw[0][i]);
            dev_atomic_u64 a1ref(g_hw[1][i]);
            a0ref.store(pack_h(h0[i], 0u), cuda::memory_order_relaxed);
            a1ref.store(((u64)0xFFFFFFFFu << 32), cuda::memory_order_relaxed);
        }
    }
}

// ================= Phase 2: persistent recurrence, single-bar + backoff poll ======
// 32 CTAs x 512 threads.  CTA c owns hidden units [16c,16c+16) -> 64 gate rows
// (row q: gate = q>>4, unit = q&15).
// Warp-pair p (warps 2p,2p+1) handles all 64 rows x cols [64p, 64p+64); thread
// (pair p, half, lane): row q = half*32+lane; W slice in 64 registers; each lane
// polls TWO tagged L2 h-words.
// KEY: the poll uses truncated-binary NANOSLEEP backoff (20ns -> 80ns cap)
// between probes.  R13's free-running polls put ~6.4 KB/cyc of sector traffic
// on L2 -- at the ~6.3 KB/cyc LTS cap -- so every consumer's spin inflated
// everyone's RT (explains R13 null, R12 8x-traffic blowup, R10 padding
// regression).  Backoff cuts steady-state poll traffic ~5x below the cap;
// the first probe still issues immediately (fast path unchanged).
// Partials -> s_part[parity][row][chunk] (transposed, stride 9).  ONE
// __syncthreads per step.  Tail is 64-wide: thread (W in {0,1}, lane l) handles
// gate l>>3 of unit W*8+(l&7): 8 LDS + fixed-tree sum + ONE activation each,
// in-warp shfl gathers the 4 gates, lanes 0..7 do the cell update and publish.
// Safety: s_part parity + bar-gated publishes; g_hw parity via the R7
// cross-CTA consume-before-overwrite chain.
__global__ void __launch_bounds__(TPB, 1)
lstm_persist(const float* __restrict__ W_hh,
             const float* __restrict__ c0,
             const float* __restrict__ fc_w,
             const float* __restrict__ fc_b,
             float* __restrict__ out)
{
    const int c    = blockIdx.x;
    const int t    = threadIdx.x;
    const int warp = t >> 5;
    const int lane = t & 31;
    const int pair = warp >> 1;            // 0..7  (column chunk)
    const int half = warp & 1;             // 0/1
    const int q    = (half << 5) | lane;   // row in CTA, 0..63
    const int grow = (q >> 4) * HIDN + (c << 4) + (q & 15);  // global gate row

    const int unitA = (pair << 6) + lane;        // first polled unit
    const int unitB = (pair << 6) + 32 + lane;   // second polled unit

    // tail mapping (threads 0..63): gate tg, local unit tu, row tq
    const int tg = lane >> 3;              // 0..3
    const int tu = ((warp & 1) << 3) | (lane & 7);   // 0..15 (warps 0,1 only)
    const int tq = (tg << 4) | tu;         // row handled by this tail thread

    __shared__ float s_part[2][64][9];     // [parity][row][chunk], stride 9
    __shared__ float red[16];

    // ---- load W_hh slice into registers (kept for all 300 steps) ----
    float w[64];
    {
        const float4* wrow =
            reinterpret_cast<const float4*>(W_hh + (size_t)grow * HIDN + (pair << 6));
        #pragma unroll
        for (int i = 0; i < 16; ++i) {
            float4 v = wrow[i];
            w[4 * i + 0] = v.x; w[4 * i + 1] = v.y;
            w[4 * i + 2] = v.z; w[4 * i + 3] = v.w;
        }
    }

    float cv = 0.f, hv = 0.f;              // state: lanes 0..7 of warps 0,1
    if (t < 64 && (lane >> 3) == 0) cv = c0[(c << 4) + tu];

    for (int step = 0; step < TSTEPS; ++step) {
        const int buf = step & 1;          // h-buffer parity AND s_part parity
        const unsigned utag = (unsigned)step;

        // tail threads prefetch their input-side gate value (in flight during poll)
        float pre_g = 0.f;
        if (t < 64) pre_g = __ldg(&g_pre[(size_t)step * G4 + tg * HIDN + (c << 4) + tu]);

        // ---- backoff poll of the two tagged words ----
        float vA, vB;
        {
            dev_atomic_u64 ra(g_hw[buf][unitA]);
            dev_atomic_u64 rb(g_hw[buf][unitB]);
            u64 a = ra.load(cuda::memory_order_relaxed);   // both probes in flight
            u64 b = rb.load(cuda::memory_order_relaxed);
            unsigned ns = 20;
            int guard = 0;
            while (((unsigned)(a >> 32) != utag || (unsigned)(b >> 32) != utag) &&
                   ++guard < SPIN_GUARD) {
                __nanosleep(ns);                            // throttle: keeps chip-wide
                ns = (ns < 80u) ? (ns << 1) : 80u;          // poll traffic under LTS cap
                if ((unsigned)(a >> 32) != utag) a = ra.load(cuda::memory_order_relaxed);
                if ((unsigned)(b >> 32) != utag) b = rb.load(cuda::memory_order_relaxed);
            }
            vA = __uint_as_float((unsigned)a);
            vB = __uint_as_float((unsigned)b);
        }

        // ---- 64-MAC dot via shfl broadcast (no smem staging) ----
        float a0 = 0.f, a1 = 0.f, a2 = 0.f, a3 = 0.f;
        #pragma unroll
        for (int k = 0; k < 32; k += 4) {
            a0 = fmaf(w[k + 0], __shfl_sync(0xffffffffu, vA, k + 0), a0);
            a1 = fmaf(w[k + 1], __shfl_sync(0xffffffffu, vA, k + 1), a1);
            a2 = fmaf(w[k + 2], __shfl_sync(0xffffffffu, vA, k + 2), a2);
            a3 = fmaf(w[k + 3], __shfl_sync(0xffffffffu, vA, k + 3), a3);
        }
        #pragma unroll
        for (int k = 0; k < 32; k += 4) {
            a0 = fmaf(w[32 + k + 0], __shfl_sync(0xffffffffu, vB, k + 0), a0);
            a1 = fmaf(w[32 + k + 1], __shfl_sync(0xffffffffu, vB, k + 1), a1);
            a2 = fmaf(w[32 + k + 2], __shfl_sync(0xffffffffu, vB, k + 2), a2);
            a3 = fmaf(w[32 + k + 3], __shfl_sync(0xffffffffu, vB, k + 3), a3);
        }
        s_part[buf][q][pair] = (a0 + a1) + (a2 + a3);

        __syncthreads();                   // the ONLY barrier in the step

        // ---- tail (t<64): reduce own row, activate, gather gates, publish ----
        if (t < 64) {
            const float* pr = s_part[buf][tq];
            float s01 = (pr[0] + pr[1]) + (pr[2] + pr[3]);
            float s23 = (pr[4] + pr[5]) + (pr[6] + pr[7]);
            float gsum = (s01 + s23) + pre_g;
            float act = (tg == 2) ? tanh_f(gsum) : sigm(gsum);

            // gather the 4 gates of unit tu into lanes 0..7 (within this warp)
            const float i_ = __shfl_sync(0xffffffffu, act, (lane & 7) + 0);
            const float f_ = __shfl_sync(0xffffffffu, act, (lane & 7) + 8);
            const float g_ = __shfl_sync(0xffffffffu, act, (lane & 7) + 16);
            const float o_ = __shfl_sync(0xffffffffu, act, (lane & 7) + 24);

            if (tg == 0) {                 // lanes 0..7: cell update + publish
                float cn = fmaf(f_, cv, i_ * g_);
                cv = cn;
                hv = o_ * tanh_f(cn);
                dev_atomic_u64 hdst(g_hw[buf ^ 1][(c << 4) + tu]);
                hdst.store(pack_h(hv, (unsigned)(step + 1)), cuda::memory_order_relaxed);
            }
        }
        // no trailing sync: parity slot reuse (s+2) is bar-gated behind the tail's
        // reads through the h-tag chain
    }

    // ---- outputs: h and c straight from the publishing threads ----
    if (t < 64 && tg == 0) {
        out[1 + ((c << 4) + tu)]   = hv;
        out[513 + ((c << 4) + tu)] = cv;
    }

    // ---- CTA 0: final fc once every word carries tag TSTEPS ----
    if (c == 0) {
        float hfin;
        {
            dev_atomic_u64 href(g_hw[TSTEPS & 1][t]);   // TSTEPS even -> buf 0
            u64 word = href.load(cuda::memory_order_relaxed);
            int guard = 0;
            while ((unsigned)(word >> 32) != (unsigned)TSTEPS &&
                   ++guard < SPIN_GUARD) {
                __nanosleep(40);
                word = href.load(cuda::memory_order_relaxed);
            }
            hfin = __uint_as_float((unsigned)word);
        }
        float p = hfin * fc_w[t];
        #pragma unroll
        for (int o = 16; o > 0; o >>= 1) p += __shfl_down_sync(0xffffffffu, p, o);
        if ((t & 31) == 0) red[t >> 5] = p;
        __syncthreads();
        if (t == 0) {
            float acc = fc_b[0];
            #pragma unroll
            for (int i = 0; i < 16; ++i) acc += red[i];
            out[0] = sigm(acc);
        }
    }
}

// ================= launch =================
extern "C" void kernel_launch(void* const* d_in, const int* in_sizes, int n_in,
                              void* d_out, int out_size)
{
    const int*   x     = (const int*)  d_in[0];
    const float* h0    = (const float*)d_in[1];
    const float* c0    = (const float*)d_in[2];
    const float* emb   = (const float*)d_in[3];
    const float* W_ih  = (const float*)d_in[4];
    const float* W_hh  = (const float*)d_in[5];
    const float* b_ih  = (const float*)d_in[6];
    const float* b_hh  = (const float*)d_in[7];
    const float* fc_w  = (const float*)d_in[8];
    const float* fc_b  = (const float*)d_in[9];
    float* out = (float*)d_out;

    dim3 pgrid(G4 / 16, (TSTEPS + 15) / 16);   // 128 x 19
    pre_kernel<<<pgrid, 256>>>(x, emb, W_ih, b_ih, b_hh, h0);
    lstm_persist<<<NCTA, TPB>>>(W_hh, c0, fc_w, fc_b, out);
}

// round 16
// speedup vs baseline: 5.2368x; 5.2368x over previous
#include <cuda_runtime.h>
#include <cuda/atomic>
#include <cstdint>

#define TSTEPS 300
#define HIDN   512
#define EMBD   300
#define G4     2048      // 4*HIDN
#define NCTA   32
#define TPB    512
#define SPIN_GUARD (1 << 16)

typedef unsigned long long u64;

// ---------------- scratch (static __device__, no allocs) ----------------
__device__ __align__(16) float g_pre[TSTEPS * G4]; // input-side gates (+biases)
__device__ __align__(16) u64   g_hw[2][HIDN];      // tagged hidden words: (tag<<32)|bits
                                                   // tag s = "h after s steps"

using dev_atomic_u64 = cuda::atomic_ref<u64, cuda::thread_scope_device>;

__device__ __forceinline__ u64 pack_h(float v, unsigned tag) {
    return ((u64)tag << 32) | (u64)__float_as_uint(v);
}

__device__ __forceinline__ float sigm(float x) { return 1.f / (1.f + __expf(-x)); }
__device__ __forceinline__ float tanh_f(float x) {
    // overflow-safe: tanh(x) = sign(x) * (1 - 2/(exp(2|x|)+1))
    float e = __expf(2.f * fabsf(x));
    float r = 1.f - 2.f / (e + 1.f);
    return copysignf(r, x);
}

// ================= Phase 1: tiled GEMM  pre[t][r] = W_ih @ emb[x[t]] + biases =====
// grid (32, 5), block 256.  Block tile: 64 rows x 64 timesteps; 4x4 per thread;
// K=300 in chunks of 16 through smem (both operands transposed to [k][.]).
#define KCH 16

__global__ void __launch_bounds__(256, 4)
pre_kernel(const int* __restrict__ x,
           const float* __restrict__ emb,
           const float* __restrict__ W_ih,
           const float* __restrict__ b_ih,
           const float* __restrict__ b_hh,
           const float* __restrict__ h0)
{
    __shared__ float Ws[KCH][68];   // Ws[k][r]  (stride 68: conflict-light)
    __shared__ float Es[KCH][68];   // Es[k][t]

    const int rB  = blockIdx.x * 64;
    const int tB  = blockIdx.y * 64;
    const int tid = threadIdx.x;

    // loader roles: lr = row (for W) / timestep (for E), lk = k offset (0,4,8,12)
    const int lr = tid >> 2;            // 0..63
    const int lk = (tid & 3) << 2;      // 0,4,8,12

    const int  t_g    = tB + lr;
    const bool tvalid = (t_g < TSTEPS);
    size_t ebase = 0;
    if (tvalid) ebase = (size_t)x[t_g] * EMBD;

    // compute roles: 4x4 micro-tile at (rB + r0.., tB + t0..)
    const int r0 = (tid >> 4) << 2;     // 0,4,...,60
    const int t0 = (tid & 15) << 2;     // 0,4,...,60

    float acc[4][4];
    #pragma unroll
    for (int i = 0; i < 4; ++i)
        #pragma unroll
        for (int j = 0; j < 4; ++j) acc[i][j] = 0.f;

    for (int kb = 0; kb < EMBD; kb += KCH) {
        const int kc = (EMBD - kb < KCH) ? (EMBD - kb) : KCH;   // 16 or 12

        __syncthreads();               // previous chunk fully consumed
        if (lk < kc) {                 // kc is 16 or 12=3 float4s -> lk<kc exact
            float4 wv = *reinterpret_cast<const float4*>(
                W_ih + (size_t)(rB + lr) * EMBD + kb + lk);
            Ws[lk + 0][lr] = wv.x; Ws[lk + 1][lr] = wv.y;
            Ws[lk + 2][lr] = wv.z; Ws[lk + 3][lr] = wv.w;
            float4 ev = make_float4(0.f, 0.f, 0.f, 0.f);
            if (tvalid) ev = *reinterpret_cast<const float4*>(emb + ebase + kb + lk);
            Es[lk + 0][lr] = ev.x; Es[lk + 1][lr] = ev.y;
            Es[lk + 2][lr] = ev.z; Es[lk + 3][lr] = ev.w;
        }
        __syncthreads();

        #pragma unroll 4
        for (int k = 0; k < kc; ++k) {
            float4 wv = *reinterpret_cast<const float4*>(&Ws[k][r0]);
            float4 ev = *reinterpret_cast<const float4*>(&Es[k][t0]);
            acc[0][0] = fmaf(wv.x, ev.x, acc[0][0]);
            acc[0][1] = fmaf(wv.x, ev.y, acc[0][1]);
            acc[0][2] = fmaf(wv.x, ev.z, acc[0][2]);
            acc[0][3] = fmaf(wv.x, ev.w, acc[0][3]);
            acc[1][0] = fmaf(wv.y, ev.x, acc[1][0]);
            acc[1][1] = fmaf(wv.y, ev.y, acc[1][1]);
            acc[1][2] = fmaf(wv.y, ev.z, acc[1][2]);
            acc[1][3] = fmaf(wv.y, ev.w, acc[1][3]);
            acc[2][0] = fmaf(wv.z, ev.x, acc[2][0]);
            acc[2][1] = fmaf(wv.z, ev.y, acc[2][1]);
            acc[2][2] = fmaf(wv.z, ev.z, acc[2][2]);
            acc[2][3] = fmaf(wv.z, ev.w, acc[2][3]);
            acc[3][0] = fmaf(wv.w, ev.x, acc[3][0]);
            acc[3][1] = fmaf(wv.w, ev.y, acc[3][1]);
            acc[3][2] = fmaf(wv.w, ev.z, acc[3][2]);
            acc[3][3] = fmaf(wv.w, ev.w, acc[3][3]);
        }
    }

    // biases, then float4 stores along r (contiguous)
    {
        float4 bi = *reinterpret_cast<const float4*>(b_ih + rB + r0);
        float4 bh = *reinterpret_cast<const float4*>(b_hh + rB + r0);
        float bb0 = bi.x + bh.x, bb1 = bi.y + bh.y;
        float bb2 = bi.z + bh.z, bb3 = bi.w + bh.w;
        #pragma unroll
        for (int j = 0; j < 4; ++j) {
            int tt = tB + t0 + j;
            if (tt < TSTEPS) {
                float4 o;
                o.x = acc[0][j] + bb0; o.y = acc[1][j] + bb1;
                o.z = acc[2][j] + bb2; o.w = acc[3][j] + bb3;
                *reinterpret_cast<float4*>(&g_pre[(size_t)tt * G4 + rB + r0]) = o;
            }
        }
    }

    // block (0,0): seed h words with tag 0 and poison the other buffer's tags
    if (blockIdx.x == 0 && blockIdx.y == 0) {
        for (int i = tid; i < HIDN; i += 256) {
            dev_atomic_u64 a0ref(g_hw[0][i]);
            dev_atomic_u64 a1ref(g_hw[1][i]);
            a0ref.store(pack_h(h0[i], 0u), cuda::memory_order_relaxed);
            a1ref.store(((u64)0xFFFFFFFFu << 32), cuda::memory_order_relaxed);
        }
    }
}

// ================= Phase 2: persistent recurrence (R13 champion, verbatim) ========
// 32 CTAs x 512 threads.  CTA c owns hidden units [16c,16c+16) -> 64 gate rows.
// Warp-pair p handles all 64 rows x cols [64p, 64p+64); W slice in 64 registers;
// each lane free-polls TWO tagged L2 h-words (depth-2 pipelined).
// Partials -> s_part[parity][row][chunk]; ONE __syncthreads per step; 64-wide tail.
__global__ void __launch_bounds__(TPB, 1)
lstm_persist(const float* __restrict__ W_hh,
             const float* __restrict__ c0,
             const float* __restrict__ fc_w,
             const float* __restrict__ fc_b,
             float* __restrict__ out)
{
    const int c    = blockIdx.x;
    const int t    = threadIdx.x;
    const int warp = t >> 5;
    const int lane = t & 31;
    const int pair = warp >> 1;            // 0..7  (column chunk)
    const int half = warp & 1;             // 0/1
    const int q    = (half << 5) | lane;   // row in CTA, 0..63
    const int grow = (q >> 4) * HIDN + (c << 4) + (q & 15);  // global gate row

    const int unitA = (pair << 6) + lane;        // first polled unit
    const int unitB = (pair << 6) + 32 + lane;   // second polled unit

    // tail mapping (threads 0..63): gate tg, local unit tu, row tq
    const int tg = lane >> 3;              // 0..3
    const int tu = ((warp & 1) << 3) | (lane & 7);   // 0..15 (warps 0,1 only)
    const int tq = (tg << 4) | tu;         // row handled by this tail thread

    __shared__ float s_part[2][64][9];     // [parity][row][chunk], stride 9
    __shared__ float red[16];

    // ---- load W_hh slice into registers (kept for all 300 steps) ----
    float w[64];
    {
        const float4* wrow =
            reinterpret_cast<const float4*>(W_hh + (size_t)grow * HIDN + (pair << 6));
        #pragma unroll
        for (int i = 0; i < 16; ++i) {
            float4 v = wrow[i];
            w[4 * i + 0] = v.x; w[4 * i + 1] = v.y;
            w[4 * i + 2] = v.z; w[4 * i + 3] = v.w;
        }
    }

    float cv = 0.f, hv = 0.f;              // state: lanes 0..7 of warps 0,1
    if (t < 64 && (lane >> 3) == 0) cv = c0[(c << 4) + tu];

    for (int step = 0; step < TSTEPS; ++step) {
        const int buf = step & 1;          // h-buffer parity AND s_part parity
        const unsigned utag = (unsigned)step;

        // tail threads prefetch their input-side gate value (in flight during poll)
        float pre_g = 0.f;
        if (t < 64) pre_g = __ldg(&g_pre[(size_t)step * G4 + tg * HIDN + (c << 4) + tu]);

        // ---- depth-2 pipelined free poll of the two tagged words ----
        float vA = 0.f, vB = 0.f;
        {
            dev_atomic_u64 ra(g_hw[buf][unitA]);
            dev_atomic_u64 rb(g_hw[buf][unitB]);
            u64 A0 = ra.load(cuda::memory_order_relaxed);
            u64 B0 = rb.load(cuda::memory_order_relaxed);
            u64 A1 = ra.load(cuda::memory_order_relaxed);
            u64 B1 = rb.load(cuda::memory_order_relaxed);
            bool dA = false, dB = false;
            int guard = 0;
            do {
                if (!dA && (unsigned)(A0 >> 32) == utag) { vA = __uint_as_float((unsigned)A0); dA = true; }
                if (!dB && (unsigned)(B0 >> 32) == utag) { vB = __uint_as_float((unsigned)B0); dB = true; }
                if (dA && dB) break;
                if (!dA) { A0 = A1; A1 = ra.load(cuda::memory_order_relaxed); }
                if (!dB) { B0 = B1; B1 = rb.load(cuda::memory_order_relaxed); }
            } while (++guard < SPIN_GUARD);
            if (!dA) vA = __uint_as_float((unsigned)A0);   // guard-expiry fallback
            if (!dB) vB = __uint_as_float((unsigned)B0);
        }

        // ---- 64-MAC dot via shfl broadcast (no smem staging) ----
        float a0 = 0.f, a1 = 0.f, a2 = 0.f, a3 = 0.f;
        #pragma unroll
        for (int k = 0; k < 32; k += 4) {
            a0 = fmaf(w[k + 0], __shfl_sync(0xffffffffu, vA, k + 0), a0);
            a1 = fmaf(w[k + 1], __shfl_sync(0xffffffffu, vA, k + 1), a1);
            a2 = fmaf(w[k + 2], __shfl_sync(0xffffffffu, vA, k + 2), a2);
            a3 = fmaf(w[k + 3], __shfl_sync(0xffffffffu, vA, k + 3), a3);
        }
        #pragma unroll
        for (int k = 0; k < 32; k += 4) {
            a0 = fmaf(w[32 + k + 0], __shfl_sync(0xffffffffu, vB, k + 0), a0);
            a1 = fmaf(w[32 + k + 1], __shfl_sync(0xffffffffu, vB, k + 1), a1);
            a2 = fmaf(w[32 + k + 2], __shfl_sync(0xffffffffu, vB, k + 2), a2);
            a3 = fmaf(w[32 + k + 3], __shfl_sync(0xffffffffu, vB, k + 3), a3);
        }
        s_part[buf][q][pair] = (a0 + a1) + (a2 + a3);

        __syncthreads();                   // the ONLY barrier in the step

        // ---- tail (t<64): reduce own row, activate, gather gates, publish ----
        if (t < 64) {
            const float* pr = s_part[buf][tq];
            float s01 = (pr[0] + pr[1]) + (pr[2] + pr[3]);
            float s23 = (pr[4] + pr[5]) + (pr[6] + pr[7]);
            float gsum = (s01 + s23) + pre_g;
            float act = (tg == 2) ? tanh_f(gsum) : sigm(gsum);

            // gather the 4 gates of unit tu into lanes 0..7 (within this warp)
            const float i_ = __shfl_sync(0xffffffffu, act, (lane & 7) + 0);
            const float f_ = __shfl_sync(0xffffffffu, act, (lane & 7) + 8);
            const float g_ = __shfl_sync(0xffffffffu, act, (lane & 7) + 16);
            const float o_ = __shfl_sync(0xffffffffu, act, (lane & 7) + 24);

            if (tg == 0) {                 // lanes 0..7: cell update + publish
                float cn = fmaf(f_, cv, i_ * g_);
                cv = cn;
                hv = o_ * tanh_f(cn);
                dev_atomic_u64 hdst(g_hw[buf ^ 1][(c << 4) + tu]);
                hdst.store(pack_h(hv, (unsigned)(step + 1)), cuda::memory_order_relaxed);
            }
        }
        // no trailing sync: parity slot reuse (s+2) is bar-gated behind the tail's
        // reads through the h-tag chain
    }

    // ---- outputs: h and c straight from the publishing threads ----
    if (t < 64 && tg == 0) {
        out[1 + ((c << 4) + tu)]   = hv;
        out[513 + ((c << 4) + tu)] = cv;
    }

    // ---- CTA 0: final fc once every word carries tag TSTEPS ----
    if (c == 0) {
        float hfin;
        {
            dev_atomic_u64 href(g_hw[TSTEPS & 1][t]);   // TSTEPS even -> buf 0
            u64 word;
            int guard = 0;
            do {
                word = href.load(cuda::memory_order_relaxed);
            } while ((unsigned)(word >> 32) != (unsigned)TSTEPS &&
                     ++guard < SPIN_GUARD);
            hfin = __uint_as_float((unsigned)word);
        }
        float p = hfin * fc_w[t];
        #pragma unroll
        for (int o = 16; o > 0; o >>= 1) p += __shfl_down_sync(0xffffffffu, p, o);
        if ((t & 31) == 0) red[t >> 5] = p;
        __syncthreads();
        if (t == 0) {
            float acc = fc_b[0];
            #pragma unroll
            for (int i = 0; i < 16; ++i) acc += red[i];
            out[0] = sigm(acc);
        }
    }
}

// ================= launch =================
extern "C" void kernel_launch(void* const* d_in, const int* in_sizes, int n_in,
                              void* d_out, int out_size)
{
    const int*   x     = (const int*)  d_in[0];
    const float* h0    = (const float*)d_in[1];
    const float* c0    = (const float*)d_in[2];
    const float* emb   = (const float*)d_in[3];
    const float* W_ih  = (const float*)d_in[4];
    const float* W_hh  = (const float*)d_in[5];
    const float* b_ih  = (const float*)d_in[6];
    const float* b_hh  = (const float*)d_in[7];
    const float* fc_w  = (const float*)d_in[8];
    const float* fc_b  = (const float*)d_in[9];
    float* out = (float*)d_out;

    dim3 pgrid(G4 / 64, (TSTEPS + 63) / 64);   // 32 x 5 tiles of 64x64
    pre_kernel<<<pgrid, 256>>>(x, emb, W_ih, b_ih, b_hh, h0);
    lstm_persist<<<NCTA, TPB>>>(W_hh, c0, fc_w, fc_b, out);
}

// round 17
// speedup vs baseline: 5.7777x; 1.1033x over previous
#include <cuda_runtime.h>
#include <cuda/atomic>
#include <cstdint>

#define TSTEPS 300
#define HIDN   512
#define EMBD   300
#define G4     2048      // 4*HIDN
#define NCTA   64
#define TPB    256
#define SPIN_GUARD (1 << 16)

typedef unsigned long long u64;

// ---------------- scratch (static __device__, no allocs) ----------------
__device__ __align__(16) float g_pre[TSTEPS * G4]; // input-side gates (+biases)
__device__ __align__(16) u64   g_hw[2][HIDN];      // tagged hidden words: (tag<<32)|bits
                                                   // tag s = "h after s steps"

using dev_atomic_u64 = cuda::atomic_ref<u64, cuda::thread_scope_device>;

__device__ __forceinline__ u64 pack_h(float v, unsigned tag) {
    return ((u64)tag << 32) | (u64)__float_as_uint(v);
}

__device__ __forceinline__ float sigm(float x) { return 1.f / (1.f + __expf(-x)); }
__device__ __forceinline__ float tanh_f(float x) {
    // overflow-safe: tanh(x) = sign(x) * (1 - 2/(exp(2|x|)+1))
    float e = __expf(2.f * fabsf(x));
    float r = 1.f - 2.f / (e + 1.f);
    return copysignf(r, x);
}

// ================= Phase 1: tiled GEMM  pre[t][r] = W_ih @ emb[x[t]] + biases =====
// grid (32, 5), block 256.  Block tile: 64 rows x 64 timesteps; 4x4 per thread;
// K=300 in chunks of 16 through smem (both operands transposed to [k][.]).
#define KCH 16

__global__ void __launch_bounds__(256, 4)
pre_kernel(const int* __restrict__ x,
           const float* __restrict__ emb,
           const float* __restrict__ W_ih,
           const float* __restrict__ b_ih,
           const float* __restrict__ b_hh,
           const float* __restrict__ h0)
{
    __shared__ float Ws[KCH][68];   // Ws[k][r]  (stride 68: conflict-light)
    __shared__ float Es[KCH][68];   // Es[k][t]

    const int rB  = blockIdx.x * 64;
    const int tB  = blockIdx.y * 64;
    const int tid = threadIdx.x;

    // loader roles: lr = row (for W) / timestep (for E), lk = k offset (0,4,8,12)
    const int lr = tid >> 2;            // 0..63
    const int lk = (tid & 3) << 2;      // 0,4,8,12

    const int  t_g    = tB + lr;
    const bool tvalid = (t_g < TSTEPS);
    size_t ebase = 0;
    if (tvalid) ebase = (size_t)x[t_g] * EMBD;

    // compute roles: 4x4 micro-tile at (rB + r0.., tB + t0..)
    const int r0 = (tid >> 4) << 2;     // 0,4,...,60
    const int t0 = (tid & 15) << 2;     // 0,4,...,60

    float acc[4][4];
    #pragma unroll
    for (int i = 0; i < 4; ++i)
        #pragma unroll
        for (int j = 0; j < 4; ++j) acc[i][j] = 0.f;

    for (int kb = 0; kb < EMBD; kb += KCH) {
        const int kc = (EMBD - kb < KCH) ? (EMBD - kb) : KCH;   // 16 or 12

        __syncthreads();               // previous chunk fully consumed
        if (lk < kc) {
            float4 wv = *reinterpret_cast<const float4*>(
                W_ih + (size_t)(rB + lr) * EMBD + kb + lk);
            Ws[lk + 0][lr] = wv.x; Ws[lk + 1][lr] = wv.y;
            Ws[lk + 2][lr] = wv.z; Ws[lk + 3][lr] = wv.w;
            float4 ev = make_float4(0.f, 0.f, 0.f, 0.f);
            if (tvalid) ev = *reinterpret_cast<const float4*>(emb + ebase + kb + lk);
            Es[lk + 0][lr] = ev.x; Es[lk + 1][lr] = ev.y;
            Es[lk + 2][lr] = ev.z; Es[lk + 3][lr] = ev.w;
        }
        __syncthreads();

        #pragma unroll 4
        for (int k = 0; k < kc; ++k) {
            float4 wv = *reinterpret_cast<const float4*>(&Ws[k][r0]);
            float4 ev = *reinterpret_cast<const float4*>(&Es[k][t0]);
            acc[0][0] = fmaf(wv.x, ev.x, acc[0][0]);
            acc[0][1] = fmaf(wv.x, ev.y, acc[0][1]);
            acc[0][2] = fmaf(wv.x, ev.z, acc[0][2]);
            acc[0][3] = fmaf(wv.x, ev.w, acc[0][3]);
            acc[1][0] = fmaf(wv.y, ev.x, acc[1][0]);
            acc[1][1] = fmaf(wv.y, ev.y, acc[1][1]);
            acc[1][2] = fmaf(wv.y, ev.z, acc[1][2]);
            acc[1][3] = fmaf(wv.y, ev.w, acc[1][3]);
            acc[2][0] = fmaf(wv.z, ev.x, acc[2][0]);
            acc[2][1] = fmaf(wv.z, ev.y, acc[2][1]);
            acc[2][2] = fmaf(wv.z, ev.z, acc[2][2]);
            acc[2][3] = fmaf(wv.z, ev.w, acc[2][3]);
            acc[3][0] = fmaf(wv.w, ev.x, acc[3][0]);
            acc[3][1] = fmaf(wv.w, ev.y, acc[3][1]);
            acc[3][2] = fmaf(wv.w, ev.z, acc[3][2]);
            acc[3][3] = fmaf(wv.w, ev.w, acc[3][3]);
        }
    }

    // biases, then float4 stores along r (contiguous)
    {
        float4 bi = *reinterpret_cast<const float4*>(b_ih + rB + r0);
        float4 bh = *reinterpret_cast<const float4*>(b_hh + rB + r0);
        float bb0 = bi.x + bh.x, bb1 = bi.y + bh.y;
        float bb2 = bi.z + bh.z, bb3 = bi.w + bh.w;
        #pragma unroll
        for (int j = 0; j < 4; ++j) {
            int tt = tB + t0 + j;
            if (tt < TSTEPS) {
                float4 o;
                o.x = acc[0][j] + bb0; o.y = acc[1][j] + bb1;
                o.z = acc[2][j] + bb2; o.w = acc[3][j] + bb3;
                *reinterpret_cast<float4*>(&g_pre[(size_t)tt * G4 + rB + r0]) = o;
            }
        }
    }

    // block (0,0): seed h words with tag 0 and poison the other buffer's tags
    if (blockIdx.x == 0 && blockIdx.y == 0) {
        for (int i = tid; i < HIDN; i += 256) {
            dev_atomic_u64 a0ref(g_hw[0][i]);
            dev_atomic_u64 a1ref(g_hw[1][i]);
            a0ref.store(pack_h(h0[i], 0u), cuda::memory_order_relaxed);
            a1ref.store(((u64)0xFFFFFFFFu << 32), cuda::memory_order_relaxed);
        }
    }
}

// ================= Phase 2: persistent recurrence, 64 slim CTAs ===================
// 64 CTAs x 256 threads.  CTA c owns hidden units [8c,8c+8) -> 32 gate rows
// (row l: gate = l>>3, unit = l&7).  Warp w (0..7) = column chunk [64w,64w+64);
// lane l = row.  W slice in 64 registers; each lane free-polls TWO tagged L2
// h-words (depth-2 pipelined; the measured-champion poll).
// WHY 64x256 (R17): the 32x512 plateau (~2.8K cyc/step, R7/R11/R13) is issue-
// bound INSIDE the CTA: 16 warps x ~140 instr on one SM = ~560 cyc of issue on
// the step's serial path, plus a 16-warp bar.  Halving warps/SM halves that;
// the tail becomes one warp-synchronous warp.  Poll traffic doubles (64 CTAs x
// 512 words) -- measured ~neutral at 2x (R13).
// Partials -> s_part[parity][row][chunk] (stride 9).  ONE __syncthreads/step.
// Safety: s_part parity + bar-gated publishes; g_hw parity via the R7
// cross-CTA consume-before-overwrite chain.
__global__ void __launch_bounds__(TPB, 1)
lstm_persist(const float* __restrict__ W_hh,
             const float* __restrict__ c0,
             const float* __restrict__ fc_w,
             const float* __restrict__ fc_b,
             float* __restrict__ out)
{
    const int c  = blockIdx.x;             // 0..63
    const int t  = threadIdx.x;            // 0..255
    const int w8 = t >> 5;                 // warp = column chunk 0..7
    const int l  = t & 31;                 // lane = row 0..31
    const int grow = (l >> 3) * HIDN + (c << 3) + (l & 7);   // global gate row

    const int unitA = (w8 << 6) + l;       // first polled unit
    const int unitB = (w8 << 6) + 32 + l;  // second polled unit

    __shared__ float s_part[2][32][9];     // [parity][row][chunk], stride 9
    __shared__ float red[8];

    // ---- load W_hh slice into registers (kept for all 300 steps) ----
    float w[64];
    {
        const float4* wrow =
            reinterpret_cast<const float4*>(W_hh + (size_t)grow * HIDN + (w8 << 6));
        #pragma unroll
        for (int i = 0; i < 16; ++i) {
            float4 v = wrow[i];
            w[4 * i + 0] = v.x; w[4 * i + 1] = v.y;
            w[4 * i + 2] = v.z; w[4 * i + 3] = v.w;
        }
    }

    float cv = 0.f, hv = 0.f;              // state: lanes 0..7 of warp 0
    if (t < 8) cv = c0[(c << 3) + t];

    for (int step = 0; step < TSTEPS; ++step) {
        const int buf = step & 1;          // h-buffer parity AND s_part parity
        const unsigned utag = (unsigned)step;

        // warp 0 prefetches the input-side gate values (in flight during poll)
        float pre_g = 0.f;
        if (t < 32) pre_g = __ldg(&g_pre[(size_t)step * G4 + grow]);

        // ---- depth-2 pipelined free poll of the two tagged words ----
        float vA = 0.f, vB = 0.f;
        {
            dev_atomic_u64 ra(g_hw[buf][unitA]);
            dev_atomic_u64 rb(g_hw[buf][unitB]);
            u64 A0 = ra.load(cuda::memory_order_relaxed);
            u64 B0 = rb.load(cuda::memory_order_relaxed);
            u64 A1 = ra.load(cuda::memory_order_relaxed);
            u64 B1 = rb.load(cuda::memory_order_relaxed);
            bool dA = false, dB = false;
            int guard = 0;
            do {
                if (!dA && (unsigned)(A0 >> 32) == utag) { vA = __uint_as_float((unsigned)A0); dA = true; }
                if (!dB && (unsigned)(B0 >> 32) == utag) { vB = __uint_as_float((unsigned)B0); dB = true; }
                if (dA && dB) break;
                if (!dA) { A0 = A1; A1 = ra.load(cuda::memory_order_relaxed); }
                if (!dB) { B0 = B1; B1 = rb.load(cuda::memory_order_relaxed); }
            } while (++guard < SPIN_GUARD);
            if (!dA) vA = __uint_as_float((unsigned)A0);   // guard-expiry fallback
            if (!dB) vB = __uint_as_float((unsigned)B0);
        }

        // ---- 64-MAC dot via shfl broadcast (no smem staging) ----
        float a0 = 0.f, a1 = 0.f, a2 = 0.f, a3 = 0.f;
        #pragma unroll
        for (int k = 0; k < 32; k += 4) {
            a0 = fmaf(w[k + 0], __shfl_sync(0xffffffffu, vA, k + 0), a0);
            a1 = fmaf(w[k + 1], __shfl_sync(0xffffffffu, vA, k + 1), a1);
            a2 = fmaf(w[k + 2], __shfl_sync(0xffffffffu, vA, k + 2), a2);
            a3 = fmaf(w[k + 3], __shfl_sync(0xffffffffu, vA, k + 3), a3);
        }
        #pragma unroll
        for (int k = 0; k < 32; k += 4) {
            a0 = fmaf(w[32 + k + 0], __shfl_sync(0xffffffffu, vB, k + 0), a0);
            a1 = fmaf(w[32 + k + 1], __shfl_sync(0xffffffffu, vB, k + 1), a1);
            a2 = fmaf(w[32 + k + 2], __shfl_sync(0xffffffffu, vB, k + 2), a2);
            a3 = fmaf(w[32 + k + 3], __shfl_sync(0xffffffffu, vB, k + 3), a3);
        }
        s_part[buf][l][w8] = (a0 + a1) + (a2 + a3);

        __syncthreads();                   // the ONLY barrier in the step

        // ---- tail: warp 0 alone (warp-synchronous; no second bar) ----
        if (t < 32) {
            const float* pr = s_part[buf][l];
            float s01 = (pr[0] + pr[1]) + (pr[2] + pr[3]);
            float s23 = (pr[4] + pr[5]) + (pr[6] + pr[7]);
            float gsum = (s01 + s23) + pre_g;
            float act = ((l >> 3) == 2) ? tanh_f(gsum) : sigm(gsum);

            // gather the 4 gates of unit (l&7) into lanes 0..7
            const float i_ = __shfl_sync(0xffffffffu, act, (l & 7) + 0);
            const float f_ = __shfl_sync(0xffffffffu, act, (l & 7) + 8);
            const float g_ = __shfl_sync(0xffffffffu, act, (l & 7) + 16);
            const float o_ = __shfl_sync(0xffffffffu, act, (l & 7) + 24);

            if (l < 8) {                   // lanes 0..7: cell update + publish
                float cn = fmaf(f_, cv, i_ * g_);
                cv = cn;
                hv = o_ * tanh_f(cn);
                dev_atomic_u64 hdst(g_hw[buf ^ 1][(c << 3) + l]);
                hdst.store(pack_h(hv, (unsigned)(step + 1)), cuda::memory_order_relaxed);
            }
        }
        // no trailing sync: parity slot reuse (s+2) is bar-gated behind the tail's
        // reads through the h-tag chain
    }

    // ---- outputs: h and c straight from the publishing threads ----
    if (t < 8) {
        out[1 + ((c << 3) + t)]   = hv;
        out[513 + ((c << 3) + t)] = cv;
    }

    // ---- CTA 0: final fc once every word carries tag TSTEPS ----
    if (c == 0) {
        float h0v, h1v;
        {
            dev_atomic_u64 r0(g_hw[TSTEPS & 1][t]);        // TSTEPS even -> buf 0
            dev_atomic_u64 r1(g_hw[TSTEPS & 1][t + 256]);
            u64 w0 = r0.load(cuda::memory_order_relaxed);
            u64 w1 = r1.load(cuda::memory_order_relaxed);
            int guard = 0;
            while (((unsigned)(w0 >> 32) != (unsigned)TSTEPS ||
                    (unsigned)(w1 >> 32) != (unsigned)TSTEPS) &&
                   ++guard < SPIN_GUARD) {
                if ((unsigned)(w0 >> 32) != (unsigned)TSTEPS) w0 = r0.load(cuda::memory_order_relaxed);
                if ((unsigned)(w1 >> 32) != (unsigned)TSTEPS) w1 = r1.load(cuda::memory_order_relaxed);
            }
            h0v = __uint_as_float((unsigned)w0);
            h1v = __uint_as_float((unsigned)w1);
        }
        float p = h0v * fc_w[t] + h1v * fc_w[t + 256];
        #pragma unroll
        for (int o = 16; o > 0; o >>= 1) p += __shfl_down_sync(0xffffffffu, p, o);
        if ((t & 31) == 0) red[t >> 5] = p;
        __syncthreads();
        if (t == 0) {
            float acc = fc_b[0];
            #pragma unroll
            for (int i = 0; i < 8; ++i) acc += red[i];
            out[0] = sigm(acc);
        }
    }
}

// ================= launch =================
extern "C" void kernel_launch(void* const* d_in, const int* in_sizes, int n_in,
                              void* d_out, int out_size)
{
    const int*   x     = (const int*)  d_in[0];
    const float* h0    = (const float*)d_in[1];
    const float* c0    = (const float*)d_in[2];
    const float* emb   = (const float*)d_in[3];
    const float* W_ih  = (const float*)d_in[4];
    const float* W_hh  = (const float*)d_in[5];
    const float* b_ih  = (const float*)d_in[6];
    const float* b_hh  = (const float*)d_in[7];
    const float* fc_w  = (const float*)d_in[8];
    const float* fc_b  = (const float*)d_in[9];
    float* out = (float*)d_out;

    dim3 pgrid(G4 / 64, (TSTEPS + 63) / 64);   // 32 x 5 tiles of 64x64
    pre_kernel<<<pgrid, 256>>>(x, emb, W_ih, b_ih, b_hh, h0);
    lstm_persist<<<NCTA, TPB>>>(W_hh, c0, fc_w, fc_b, out);
}